// round 5
// baseline (speedup 1.0000x reference)
#include <cuda_runtime.h>

#define THREADS   256
#define DIN       100
#define HD        64
#define GG        10
#define NHEADS    5
#define CHUNK     25
#define MS        256      // samples per CTA
#define XSTR      260      // row stride for Xs / a0s / hid (k-major tiles)
#define W0STRIDE  4100     // heads land on disjoint bank-quad groups
#define TWSTRIDE  65

// ---- shared memory float offsets ----
#define OFF_DB0   0          // 64
#define OFF_DB1   64         // 64
#define OFF_DBB   128        // 12
#define OFF_TW0   140        // 5*65 = 325
#define OFF_B0    465        // 325
#define OFF_TW1   790        // 8
#define OFF_B1    798        // 8
#define OFF_DBW   808        // 64*12 = 768 -> 1576
#define OFF_W1H   1576       // 5*68 = 340 -> 1916 (pad to 1920)
#define OFF_DW1   1920       // 64*64 = 4096 -> 6016
#define OFF_HID   6016       // 64*260 = 16640 -> 22656   (k-major hid)
#define OFF_UNION 22656
#define OFF_DW0   OFF_UNION            // 100*64 = 6400 -> +6400
#define OFF_XS    (OFF_UNION + 6400)   // 25*260 = 6500 -> +12900
#define OFF_A0    (OFF_UNION + 12900)  // 64*260 = 16640 -> +29540
#define OFF_W0S   OFF_UNION            // phase C: 5*4100 = 20500 (a0s dead)
#define SMEM_FLOATS (OFF_UNION + 29540)     // 52196 floats
#define SMEM_BYTES  (SMEM_FLOATS * 4)       // 208,784 B -> 1 CTA/SM

typedef unsigned long long ull;
struct u2 { ull x, y; };

#define FFMA2(d, a, b, c) \
    asm("fma.rn.f32x2 %0, %1, %2, %3;" : "=l"(d) : "l"(a), "l"(b), "l"(c))

__device__ __forceinline__ ull splat2(float a) {
    ull r; asm("mov.b64 %0, {%1, %1};" : "=l"(r) : "f"(a)); return r;
}
__device__ __forceinline__ ull pack2(float a, float b) {
    ull r; asm("mov.b64 %0, {%1, %2};" : "=l"(r) : "f"(a), "f"(b)); return r;
}
__device__ __forceinline__ void unpack2(ull v, float& a, float& b) {
    asm("mov.b64 {%0, %1}, %2;" : "=f"(a), "=f"(b) : "l"(v));
}

// one k-step of the 8x8 micro-tile: 8 splats, 32 FFMA2
#define TILE_K_STEP(xa, xb, w0, w1, acc) do {                                   \
    ull xv;                                                                     \
    xv = splat2((xa).x); FFMA2(acc[0],xv,(w0).x,acc[0]); FFMA2(acc[1],xv,(w0).y,acc[1]); FFMA2(acc[2],xv,(w1).x,acc[2]); FFMA2(acc[3],xv,(w1).y,acc[3]); \
    xv = splat2((xa).y); FFMA2(acc[4],xv,(w0).x,acc[4]); FFMA2(acc[5],xv,(w0).y,acc[5]); FFMA2(acc[6],xv,(w1).x,acc[6]); FFMA2(acc[7],xv,(w1).y,acc[7]); \
    xv = splat2((xa).z); FFMA2(acc[8],xv,(w0).x,acc[8]); FFMA2(acc[9],xv,(w0).y,acc[9]); FFMA2(acc[10],xv,(w1).x,acc[10]); FFMA2(acc[11],xv,(w1).y,acc[11]); \
    xv = splat2((xa).w); FFMA2(acc[12],xv,(w0).x,acc[12]); FFMA2(acc[13],xv,(w0).y,acc[13]); FFMA2(acc[14],xv,(w1).x,acc[14]); FFMA2(acc[15],xv,(w1).y,acc[15]); \
    xv = splat2((xb).x); FFMA2(acc[16],xv,(w0).x,acc[16]); FFMA2(acc[17],xv,(w0).y,acc[17]); FFMA2(acc[18],xv,(w1).x,acc[18]); FFMA2(acc[19],xv,(w1).y,acc[19]); \
    xv = splat2((xb).y); FFMA2(acc[20],xv,(w0).x,acc[20]); FFMA2(acc[21],xv,(w0).y,acc[21]); FFMA2(acc[22],xv,(w1).x,acc[22]); FFMA2(acc[23],xv,(w1).y,acc[23]); \
    xv = splat2((xb).z); FFMA2(acc[24],xv,(w0).x,acc[24]); FFMA2(acc[25],xv,(w0).y,acc[25]); FFMA2(acc[26],xv,(w1).x,acc[26]); FFMA2(acc[27],xv,(w1).y,acc[27]); \
    xv = splat2((xb).w); FFMA2(acc[28],xv,(w0).x,acc[28]); FFMA2(acc[29],xv,(w0).y,acc[29]); FFMA2(acc[30],xv,(w1).x,acc[30]); FFMA2(acc[31],xv,(w1).y,acc[31]); \
} while (0)

__global__ void __launch_bounds__(THREADS, 1)
drnet_kernel(const float* __restrict__ dosage, const float* __restrict__ x,
             const float* __restrict__ dW0, const float* __restrict__ db0,
             const float* __restrict__ dW1, const float* __restrict__ db1,
             const float* __restrict__ dbW, const float* __restrict__ dbB,
             const float* __restrict__ W0,  const float* __restrict__ tw0,
             const float* __restrict__ b0,  const float* __restrict__ W1,
             const float* __restrict__ tw1, const float* __restrict__ b1,
             float* __restrict__ out, int B)
{
    extern __shared__ float sm[];
    const int tid  = threadIdx.x;
    const int lane = tid & 31;
    const int wid  = tid >> 5;
    // warp grid 4(M) x 2(N); thread grid in warp 8(M) x 4(N)
    const int warpM = wid & 3, warpN = wid >> 2;
    const int tm = lane & 7,   tn = lane >> 3;
    const int m0 = warpM * 64 + tm * 8;   // 8 samples
    const int n0 = warpN * 32 + tn * 8;   // 8 outputs
    const int mbase = blockIdx.x * MS;

    // ---------------- stage persistent weights ----------------
    #pragma unroll 4
    for (int i = tid; i < DIN * HD; i += THREADS) sm[OFF_DW0 + i] = dW0[i];
    #pragma unroll 4
    for (int i = tid; i < HD * HD; i += THREADS) sm[OFF_DW1 + i] = dW1[i];
    for (int i = tid; i < HD * 11; i += THREADS) {
        int k = i / 11, j = i % 11;
        sm[OFF_DBW + k * 12 + j] = dbW[i];
    }
    for (int i = tid; i < NHEADS * HD; i += THREADS) {
        int h = i / HD, j = i % HD;
        sm[OFF_W1H + h * 68 + j]       = W1[i];
        sm[OFF_TW0 + h * TWSTRIDE + j] = tw0[i];
        sm[OFF_B0  + h * TWSTRIDE + j] = b0[i];
    }
    if (tid < HD) { sm[OFF_DB0 + tid] = db0[tid]; sm[OFF_DB1 + tid] = db1[tid]; }
    if (tid < 11) sm[OFF_DBB + tid] = dbB[tid];
    if (tid < NHEADS) { sm[OFF_TW1 + tid] = tw1[tid]; sm[OFF_B1 + tid] = b1[tid]; }

    const float t = dosage[mbase + tid];

    // ================= layer0 GEMM: a0 = relu(X @ dW0 + db0) =================
    ull acc[32];
    #pragma unroll
    for (int i = 0; i < 32; i++) acc[i] = 0ull;

    #pragma unroll 1
    for (int c = 0; c < DIN / CHUNK; c++) {
        // stage Xs[k][m] transposed, global reads col-fastest (coalesced runs)
        #pragma unroll 5
        for (int i = tid; i < MS * CHUNK; i += THREADS) {
            int row = i / CHUNK, col = i % CHUNK;   // row = sample, col = k
            sm[OFF_XS + col * XSTR + row] = x[(mbase + row) * DIN + c * CHUNK + col];
        }
        __syncthreads();
        #pragma unroll 5
        for (int kk = 0; kk < CHUNK; kk++) {
            const float4* xp = (const float4*)(sm + OFF_XS + kk * XSTR + m0);
            float4 xa = xp[0], xb = xp[1];
            const u2* wp = (const u2*)(sm + OFF_DW0 + (c * CHUNK + kk) * HD + n0);
            u2 w0 = wp[0], w1 = wp[1];
            TILE_K_STEP(xa, xb, w0, w1, acc);
        }
        __syncthreads();
    }
    // bias + relu, store transposed a0s[n][m]
    {
        float bj[8];
        #pragma unroll
        for (int j = 0; j < 8; j++) bj[j] = sm[OFF_DB0 + n0 + j];
        #pragma unroll
        for (int j = 0; j < 8; j++) {
            int p = j >> 1, h = j & 1;
            float v[8];
            #pragma unroll
            for (int s = 0; s < 8; s++) {
                float e0, e1; unpack2(acc[s * 4 + p], e0, e1);
                v[s] = fmaxf((h ? e1 : e0) + bj[j], 0.0f);
            }
            float* dst = sm + OFF_A0 + (n0 + j) * XSTR + m0;
            *(float4*)dst       = make_float4(v[0], v[1], v[2], v[3]);
            *(float4*)(dst + 4) = make_float4(v[4], v[5], v[6], v[7]);
        }
    }
    __syncthreads();

    // ================= layer1 GEMM: hid = relu(a0 @ dW1 + db1) =================
    #pragma unroll
    for (int i = 0; i < 32; i++) acc[i] = 0ull;
    #pragma unroll 4
    for (int k = 0; k < HD; k++) {
        const float4* xp = (const float4*)(sm + OFF_A0 + k * XSTR + m0);
        float4 xa = xp[0], xb = xp[1];
        const u2* wp = (const u2*)(sm + OFF_DW1 + k * HD + n0);
        u2 w0 = wp[0], w1 = wp[1];
        TILE_K_STEP(xa, xb, w0, w1, acc);
    }
    {
        float bj[8];
        #pragma unroll
        for (int j = 0; j < 8; j++) bj[j] = sm[OFF_DB1 + n0 + j];
        #pragma unroll
        for (int j = 0; j < 8; j++) {
            int p = j >> 1, h = j & 1;
            float v[8];
            #pragma unroll
            for (int s = 0; s < 8; s++) {
                float e0, e1; unpack2(acc[s * 4 + p], e0, e1);
                v[s] = fmaxf((h ? e1 : e0) + bj[j], 0.0f);
            }
            float* dst = sm + OFF_HID + (n0 + j) * XSTR + m0;
            *(float4*)dst       = make_float4(v[0], v[1], v[2], v[3]);
            *(float4*)(dst + 4) = make_float4(v[4], v[5], v[6], v[7]);
        }
    }
    __syncthreads();

    // ---------------- stage W0 heads into union (a0s/Xs/dW0 dead) ----------------
    #pragma unroll 4
    for (int i = tid; i < NHEADS * HD * HD; i += THREADS) {
        int h = i >> 12, r = i & 4095;
        sm[OFF_W0S + h * W0STRIDE + r] = W0[i];
    }
    __syncthreads();

    // ================= epilogue: thread-per-sample (m = tid) =================
    int bkt = (int)floorf(t * (float)NHEADS);
    if (bkt < 0) bkt = 0;
    if (bkt > NHEADS - 1) bkt = NHEADS - 1;

    ull ho[32];
    {
        const float* twp = sm + OFF_TW0 + bkt * TWSTRIDE;
        const float* bbp = sm + OFF_B0  + bkt * TWSTRIDE;
        #pragma unroll
        for (int i = 0; i < 32; i++)
            ho[i] = pack2(fmaf(t, twp[2*i],   bbp[2*i]),
                          fmaf(t, twp[2*i+1], bbp[2*i+1]));
    }
    float logit[GG + 1];
    #pragma unroll
    for (int j = 0; j <= GG; j++) logit[j] = sm[OFF_DBB + j];

    const u2* whead = (const u2*)(sm + OFF_W0S + bkt * W0STRIDE);
    #pragma unroll 2
    for (int k = 0; k < HD; k++) {
        float a = sm[OFF_HID + k * XSTR + tid];       // conflict-free scalar LDS
        ull av = splat2(a);
        const u2* wp = whead + k * (HD / 4);
        #pragma unroll
        for (int j = 0; j < 16; j++) {
            u2 ww = wp[j];
            FFMA2(ho[2*j+0], av, ww.x, ho[2*j+0]);
            FFMA2(ho[2*j+1], av, ww.y, ho[2*j+1]);
        }
        const float4* d4 = (const float4*)(sm + OFF_DBW + k * 12);
        float4 da = d4[0], db_ = d4[1], dc = d4[2];
        logit[0] += a * da.x;  logit[1] += a * da.y;  logit[2]  += a * da.z;  logit[3] += a * da.w;
        logit[4] += a * db_.x; logit[5] += a * db_.y; logit[6]  += a * db_.z; logit[7] += a * db_.w;
        logit[8] += a * dc.x;  logit[9] += a * dc.y;  logit[10] += a * dc.z;
    }

    // softmax + grid interpolation
    float m = logit[0];
    #pragma unroll
    for (int j = 1; j <= GG; j++) m = fmaxf(m, logit[j]);
    float p[GG + 1]; float psum = 0.0f;
    #pragma unroll
    for (int j = 0; j <= GG; j++) { p[j] = expf(logit[j] - m); psum += p[j]; }
    float pinv = 1.0f / psum;

    float tB = t * (float)GG;
    float U = ceilf(tB);
    float inter = 1.0f - (U - tB);
    int Ui = (int)U;
    int Li = Ui - 1; if (Li < 0) Li = 0;
    float pL = 0.0f, pU = 0.0f;
    #pragma unroll
    for (int j = 0; j <= GG; j++) {
        pL = (j == Li) ? p[j] : pL;
        pU = (j == Ui) ? p[j] : pU;
    }
    pL *= pinv; pU *= pinv;
    float g = pL + (pU - pL) * inter;

    // head output layer
    float q = t * sm[OFF_TW1 + bkt] + sm[OFF_B1 + bkt];
    {
        const float* w1p = sm + OFF_W1H + bkt * 68;
        #pragma unroll
        for (int i = 0; i < 32; i++) {
            float lo, hi; unpack2(ho[i], lo, hi);
            q += fmaxf(lo, 0.0f) * w1p[2*i+0];
            q += fmaxf(hi, 0.0f) * w1p[2*i+1];
        }
    }

    out[mbase + tid]     = g;
    out[B + mbase + tid] = q;
}

extern "C" void kernel_launch(void* const* d_in, const int* in_sizes, int n_in,
                              void* d_out, int out_size)
{
    const float* dosage = (const float*)d_in[0];
    const float* x      = (const float*)d_in[1];
    const float* dW0    = (const float*)d_in[2];
    const float* db0    = (const float*)d_in[3];
    const float* dW1    = (const float*)d_in[4];
    const float* db1    = (const float*)d_in[5];
    const float* dbW    = (const float*)d_in[6];
    const float* dbB    = (const float*)d_in[7];
    const float* W0     = (const float*)d_in[8];
    const float* tw0    = (const float*)d_in[9];
    const float* b0     = (const float*)d_in[10];
    const float* W1     = (const float*)d_in[11];
    const float* tw1    = (const float*)d_in[12];
    const float* b1     = (const float*)d_in[13];
    float* out = (float*)d_out;

    int B = in_sizes[0];
    int blocks = B / MS;

    cudaFuncSetAttribute(drnet_kernel,
                         cudaFuncAttributeMaxDynamicSharedMemorySize, SMEM_BYTES);

    drnet_kernel<<<blocks, THREADS, SMEM_BYTES>>>(
        dosage, x, dW0, db0, dW1, db1, dbW, dbB,
        W0, tw0, b0, W1, tw1, b1, out, B);
}

// round 7
// speedup vs baseline: 1.0337x; 1.0337x over previous
#include <cuda_runtime.h>

#define THREADS   256
#define DIN       100
#define HD        64
#define GG        10
#define NHEADS    5
#define CHUNK     25
#define MS1       128      // samples per CTA, kernel1
#define MS2       256      // samples per CTA, kernel2
#define XSTR      132      // XS row stride (16B-aligned rows)
#define ASTR      128      // A0/HID row stride
#define B_MAX     262144

// ---------------- kernel1 shared layout (floats) ----------------
#define OFF_DB0   0          // 64
#define OFF_DB1   64         // 64
#define OFF_DBB   128        // 12
#define OFF_DBW   140        // 64*12 = 768 -> 908, pad 912
#define OFF_W     912        // dW0 100*64=6400 ; later dW1 64*64 in first 4096
#define OFF_XS    7312       // 25*132 = 3300
#define OFF_A0    10612      // 64*128 = 8192  (a0 k-major, then hid k-major)
#define SM1_FLOATS (OFF_A0 + 64*ASTR)      // 18804
#define SM1_BYTES  (SM1_FLOATS * 4)        // 75216 -> 3 CTAs/SM

// ---------------- kernel2 shared layout (floats) ----------------
#define K2_W0     0          // 5*4096 = 20480
#define K2_TW0    20480      // 5*64 = 320
#define K2_B0     20800      // 320
#define K2_W1     21120      // 320
#define K2_TW1    21440      // 5
#define K2_B1     21448      // 5 (pad)
#define K2_CNT    21456      // int[5]
#define K2_CUR    21461      // int[5]
#define K2_OFFS   21466      // int[6]
#define K2_PERM   21472      // int[256]
#define SM2_FLOATS 21728
#define SM2_BYTES  (SM2_FLOATS * 4)        // 86912 -> 2 CTAs/SM

__device__ float g_hid[B_MAX * HD];        // [sample][64] scratch

typedef unsigned long long ull;
struct u2 { ull x, y; };

#define FFMA2(d, a, b, c) \
    asm("fma.rn.f32x2 %0, %1, %2, %3;" : "=l"(d) : "l"(a), "l"(b), "l"(c))

__device__ __forceinline__ ull splat2(float a) {
    ull r; asm("mov.b64 %0, {%1, %1};" : "=l"(r) : "f"(a)); return r;
}
__device__ __forceinline__ ull pack2(float a, float b) {
    ull r; asm("mov.b64 %0, {%1, %2};" : "=l"(r) : "f"(a), "f"(b)); return r;
}
__device__ __forceinline__ void unpack2(ull v, float& a, float& b) {
    asm("mov.b64 {%0, %1}, %2;" : "=f"(a), "=f"(b) : "l"(v));
}

// 8 samples x 4 outputs micro-step: 16 FFMA2
#define STEP84(xa, xb, wv, acc) do {                                        \
    ull xv;                                                                 \
    xv = splat2((xa).x); FFMA2(acc[0], xv,(wv).x,acc[0]);  FFMA2(acc[1], xv,(wv).y,acc[1]);  \
    xv = splat2((xa).y); FFMA2(acc[2], xv,(wv).x,acc[2]);  FFMA2(acc[3], xv,(wv).y,acc[3]);  \
    xv = splat2((xa).z); FFMA2(acc[4], xv,(wv).x,acc[4]);  FFMA2(acc[5], xv,(wv).y,acc[5]);  \
    xv = splat2((xa).w); FFMA2(acc[6], xv,(wv).x,acc[6]);  FFMA2(acc[7], xv,(wv).y,acc[7]);  \
    xv = splat2((xb).x); FFMA2(acc[8], xv,(wv).x,acc[8]);  FFMA2(acc[9], xv,(wv).y,acc[9]);  \
    xv = splat2((xb).y); FFMA2(acc[10],xv,(wv).x,acc[10]); FFMA2(acc[11],xv,(wv).y,acc[11]); \
    xv = splat2((xb).z); FFMA2(acc[12],xv,(wv).x,acc[12]); FFMA2(acc[13],xv,(wv).y,acc[13]); \
    xv = splat2((xb).w); FFMA2(acc[14],xv,(wv).x,acc[14]); FFMA2(acc[15],xv,(wv).y,acc[15]); \
} while (0)

// ======================= kernel 1: MLP GEMMs + density =======================
__global__ void __launch_bounds__(THREADS, 3)
drnet_mlp_kernel(const float* __restrict__ dosage, const float* __restrict__ x,
                 const float* __restrict__ dW0, const float* __restrict__ db0,
                 const float* __restrict__ dW1, const float* __restrict__ db1,
                 const float* __restrict__ dbW, const float* __restrict__ dbB,
                 float* __restrict__ out, int B)
{
    extern __shared__ float sm[];
    const int tid  = threadIdx.x;
    const int lane = tid & 31;
    const int wid  = tid >> 5;
    const int warpM = wid & 1, warpN = wid >> 1;   // 2 x 4 warps
    const int tm = lane & 7,   tn = lane >> 3;     // 8 x 4 lanes
    const int m0 = warpM * 64 + tm * 8;            // 8 samples
    const int n0 = warpN * 16 + tn * 4;            // 4 outputs
    const int mbase = blockIdx.x * MS1;

    // stage dW0 + small params
    #pragma unroll 4
    for (int i = tid; i < DIN * HD; i += THREADS) sm[OFF_W + i] = dW0[i];
    for (int i = tid; i < HD * 11; i += THREADS) {
        int k = i / 11, j = i % 11;
        sm[OFF_DBW + k * 12 + j] = dbW[i];
    }
    if (tid < HD) { sm[OFF_DB0 + tid] = db0[tid]; sm[OFF_DB1 + tid] = db1[tid]; }
    if (tid < 11) sm[OFF_DBB + tid] = dbB[tid];

    // ---------------- layer0 GEMM ----------------
    ull acc[16];
    #pragma unroll
    for (int i = 0; i < 16; i++) acc[i] = 0ull;

    #pragma unroll 1
    for (int c = 0; c < DIN / CHUNK; c++) {
        for (int i = tid; i < MS1 * CHUNK; i += THREADS) {
            int row = i / CHUNK, col = i % CHUNK;
            sm[OFF_XS + col * XSTR + row] = x[(mbase + row) * DIN + c * CHUNK + col];
        }
        __syncthreads();
        #pragma unroll 5
        for (int kk = 0; kk < CHUNK; kk++) {
            const float4* xp = (const float4*)(sm + OFF_XS + kk * XSTR + m0);
            float4 xa = xp[0], xb = xp[1];
            u2 wv = *(const u2*)(sm + OFF_W + (c * CHUNK + kk) * HD + n0);
            STEP84(xa, xb, wv, acc);
        }
        __syncthreads();
    }
    // epilogue: bias+relu -> A0 k-major [n][m]
    {
        #pragma unroll
        for (int j = 0; j < 4; j++) {
            int p = j >> 1, h = j & 1;
            float bj = sm[OFF_DB0 + n0 + j];
            float v[8];
            #pragma unroll
            for (int s = 0; s < 8; s++) {
                float e0, e1; unpack2(acc[s * 2 + p], e0, e1);
                v[s] = fmaxf((h ? e1 : e0) + bj, 0.0f);
            }
            float* dst = sm + OFF_A0 + (n0 + j) * ASTR + m0;
            *(float4*)dst       = make_float4(v[0], v[1], v[2], v[3]);
            *(float4*)(dst + 4) = make_float4(v[4], v[5], v[6], v[7]);
        }
    }
    // restage dW1 over dW0 (all reads of dW0 fenced by last sync above)
    {
        const float4* src = (const float4*)dW1;
        #pragma unroll
        for (int i = tid; i < HD * HD / 4; i += THREADS)
            ((float4*)(sm + OFF_W))[i] = src[i];
    }
    __syncthreads();

    // ---------------- layer1 GEMM ----------------
    #pragma unroll
    for (int i = 0; i < 16; i++) acc[i] = 0ull;
    #pragma unroll 4
    for (int k = 0; k < HD; k++) {
        const float4* xp = (const float4*)(sm + OFF_A0 + k * ASTR + m0);
        float4 xa = xp[0], xb = xp[1];
        u2 wv = *(const u2*)(sm + OFF_W + k * HD + n0);
        STEP84(xa, xb, wv, acc);
    }
    __syncthreads();   // everyone done reading A0 before overwrite
    {
        #pragma unroll
        for (int j = 0; j < 4; j++) {
            int p = j >> 1, h = j & 1;
            float bj = sm[OFF_DB1 + n0 + j];
            float v[8];
            #pragma unroll
            for (int s = 0; s < 8; s++) {
                float e0, e1; unpack2(acc[s * 2 + p], e0, e1);
                v[s] = fmaxf((h ? e1 : e0) + bj, 0.0f);
            }
            float* dst = sm + OFF_A0 + (n0 + j) * ASTR + m0;
            *(float4*)dst       = make_float4(v[0], v[1], v[2], v[3]);
            *(float4*)(dst + 4) = make_float4(v[4], v[5], v[6], v[7]);
        }
        // global hid [sample][64]: per sample one float4 (4 consecutive outputs)
        #pragma unroll
        for (int s = 0; s < 8; s++) {
            float v[4];
            #pragma unroll
            for (int j = 0; j < 4; j++) {
                int p = j >> 1, h = j & 1;
                float e0, e1; unpack2(acc[s * 2 + p], e0, e1);
                v[j] = fmaxf((h ? e1 : e0) + sm[OFF_DB1 + n0 + j], 0.0f);
            }
            *(float4*)(g_hid + (ull)(mbase + m0 + s) * HD + n0) =
                make_float4(v[0], v[1], v[2], v[3]);
        }
    }
    __syncthreads();

    // ---------------- density (thread-per-sample, tid < 128) ----------------
    if (tid < MS1) {
        const float t = dosage[mbase + tid];
        float logit[GG + 1];
        #pragma unroll
        for (int j = 0; j <= GG; j++) logit[j] = sm[OFF_DBB + j];
        #pragma unroll 4
        for (int k = 0; k < HD; k++) {
            float a = sm[OFF_A0 + k * ASTR + tid];
            const float4* d4 = (const float4*)(sm + OFF_DBW + k * 12);
            float4 da = d4[0], db_ = d4[1], dc = d4[2];
            logit[0] += a * da.x;  logit[1] += a * da.y;  logit[2]  += a * da.z;  logit[3] += a * da.w;
            logit[4] += a * db_.x; logit[5] += a * db_.y; logit[6]  += a * db_.z; logit[7] += a * db_.w;
            logit[8] += a * dc.x;  logit[9] += a * dc.y;  logit[10] += a * dc.z;
        }
        float m = logit[0];
        #pragma unroll
        for (int j = 1; j <= GG; j++) m = fmaxf(m, logit[j]);
        float p[GG + 1]; float psum = 0.0f;
        #pragma unroll
        for (int j = 0; j <= GG; j++) { p[j] = expf(logit[j] - m); psum += p[j]; }
        float pinv = 1.0f / psum;

        float tB = t * (float)GG;
        float U = ceilf(tB);
        float inter = 1.0f - (U - tB);
        int Ui = (int)U;
        int Li = Ui - 1; if (Li < 0) Li = 0;
        float pL = 0.0f, pU = 0.0f;
        #pragma unroll
        for (int j = 0; j <= GG; j++) {
            pL = (j == Li) ? p[j] : pL;
            pU = (j == Ui) ? p[j] : pU;
        }
        pL *= pinv; pU *= pinv;
        out[mbase + tid] = pL + (pU - pL) * inter;
    }
}

// ======================= kernel 2: bucketed head =======================
__global__ void __launch_bounds__(THREADS, 2)
drnet_head_kernel(const float* __restrict__ dosage,
                  const float* __restrict__ W0,  const float* __restrict__ tw0,
                  const float* __restrict__ b0,  const float* __restrict__ W1,
                  const float* __restrict__ tw1, const float* __restrict__ b1,
                  float* __restrict__ out, int B)
{
    extern __shared__ float sm[];
    int* icnt  = (int*)(sm + K2_CNT);
    int* icur  = (int*)(sm + K2_CUR);
    int* ioffs = (int*)(sm + K2_OFFS);
    int* iperm = (int*)(sm + K2_PERM);
    const int tid = threadIdx.x;
    const int mbase = blockIdx.x * MS2;

    // stage W0 (5 heads x 64x64) + head params
    {
        const float4* src = (const float4*)W0;
        #pragma unroll 4
        for (int i = tid; i < NHEADS * HD * HD / 4; i += THREADS)
            ((float4*)(sm + K2_W0))[i] = src[i];
    }
    for (int i = tid; i < NHEADS * HD; i += THREADS) {
        sm[K2_TW0 + i] = tw0[i];
        sm[K2_B0  + i] = b0[i];
        sm[K2_W1  + i] = W1[i];
    }
    if (tid < NHEADS) { sm[K2_TW1 + tid] = tw1[tid]; sm[K2_B1 + tid] = b1[tid]; }
    if (tid < NHEADS) icnt[tid] = 0;
    __syncthreads();

    // histogram of buckets
    const float tme = dosage[mbase + tid];
    int bkt = (int)floorf(tme * (float)NHEADS);
    if (bkt < 0) bkt = 0;
    if (bkt > NHEADS - 1) bkt = NHEADS - 1;
    atomicAdd(&icnt[bkt], 1);
    __syncthreads();
    if (tid == 0) {
        int o = 0;
        #pragma unroll
        for (int h = 0; h < NHEADS; h++) { ioffs[h] = o; icur[h] = o; o += icnt[h]; }
        ioffs[NHEADS] = o;
    }
    __syncthreads();
    int slot = atomicAdd(&icur[bkt], 1);
    iperm[slot] = tid;
    __syncthreads();

    // compacted processing: position p = tid, sorted by bucket
    const int p  = tid;
    const int h  = (p >= ioffs[1]) + (p >= ioffs[2]) + (p >= ioffs[3]) + (p >= ioffs[4]);
    const int sl = iperm[p];
    const float t = dosage[mbase + sl];

    // init acc with t*tw0 + b0 (head h)
    ull acc[32];
    {
        const float* twp = sm + K2_TW0 + h * HD;
        const float* bbp = sm + K2_B0  + h * HD;
        #pragma unroll
        for (int i = 0; i < 32; i++)
            acc[i] = pack2(fmaf(t, twp[2*i],   bbp[2*i]),
                           fmaf(t, twp[2*i+1], bbp[2*i+1]));
    }
    // hid row from scratch, k-loop with warp-uniform weight broadcasts
    const float* hrow = g_hid + (ull)(mbase + sl) * HD;
    const float* wh   = sm + K2_W0 + h * (HD * HD);
    #pragma unroll 1
    for (int kc = 0; kc < 4; kc++) {
        float4 hv[4];
        #pragma unroll
        for (int i = 0; i < 4; i++)
            hv[i] = ((const float4*)hrow)[kc * 4 + i];
        #pragma unroll
        for (int kk = 0; kk < 16; kk++) {
            float a = ((const float*)hv)[kk];
            ull av = splat2(a);
            const u2* wp = (const u2*)(wh + (kc * 16 + kk) * HD);
            #pragma unroll
            for (int j = 0; j < 16; j++) {
                u2 ww = wp[j];
                FFMA2(acc[2*j+0], av, ww.x, acc[2*j+0]);
                FFMA2(acc[2*j+1], av, ww.y, acc[2*j+1]);
            }
        }
    }
    // output layer: relu dot W1[h]
    float q = fmaf(t, sm[K2_TW1 + h], sm[K2_B1 + h]);
    {
        const float* w1p = sm + K2_W1 + h * HD;
        #pragma unroll
        for (int i = 0; i < 32; i++) {
            float lo, hi; unpack2(acc[i], lo, hi);
            q += fmaxf(lo, 0.0f) * w1p[2*i+0];
            q += fmaxf(hi, 0.0f) * w1p[2*i+1];
        }
    }
    out[B + mbase + sl] = q;
}

extern "C" void kernel_launch(void* const* d_in, const int* in_sizes, int n_in,
                              void* d_out, int out_size)
{
    const float* dosage = (const float*)d_in[0];
    const float* x      = (const float*)d_in[1];
    const float* dW0    = (const float*)d_in[2];
    const float* db0    = (const float*)d_in[3];
    const float* dW1    = (const float*)d_in[4];
    const float* db1    = (const float*)d_in[5];
    const float* dbW    = (const float*)d_in[6];
    const float* dbB    = (const float*)d_in[7];
    const float* W0     = (const float*)d_in[8];
    const float* tw0    = (const float*)d_in[9];
    const float* b0     = (const float*)d_in[10];
    const float* W1     = (const float*)d_in[11];
    const float* tw1    = (const float*)d_in[12];
    const float* b1     = (const float*)d_in[13];
    float* out = (float*)d_out;

    int B = in_sizes[0];

    cudaFuncSetAttribute(drnet_mlp_kernel,
                         cudaFuncAttributeMaxDynamicSharedMemorySize, SM1_BYTES);
    cudaFuncSetAttribute(drnet_head_kernel,
                         cudaFuncAttributeMaxDynamicSharedMemorySize, SM2_BYTES);

    drnet_mlp_kernel<<<B / MS1, THREADS, SM1_BYTES>>>(
        dosage, x, dW0, db0, dW1, db1, dbW, dbB, out, B);
    drnet_head_kernel<<<B / MS2, THREADS, SM2_BYTES>>>(
        dosage, W0, tw0, b0, W1, tw1, b1, out, B);
}